// round 9
// baseline (speedup 1.0000x reference)
#include <cuda_runtime.h>
#include <cstdint>

// Problem shape (fixed by the reference): B=8, S=512, V=32000, M=32, PAD_ID=1
// NOTE: jax without x64 silently makes "int64" inputs int32 — a and mask are int32.
#define BB 8
#define SS 512
#define VV 32000
#define MM 32
#define PAD_ID 1

#define ROWS (BB * SS)          // 4096
#define THREADS 512             // 16 warps/block
#define ROWS_PER_BLOCK 16
#define NBLOCKS (ROWS / ROWS_PER_BLOCK)   // 256
#define PARTIALS_PER_B (NBLOCKS / BB)     // 32 consecutive partials per batch elem

// Scratch (device-side allocation is forbidden -> __device__ globals).
__device__ float g_partials[NBLOCKS];
__device__ unsigned int g_done = 0;   // reset to 0 by the last block each run

// One warp per (b,s) row. Lane j handles mask[b,s,j].
// logp(b,s) = logits[b,s,a] - log( sum_{j: mask_j>0} exp(logits[b,s,mask_j]) )
// Block-reduces 16 rows' logp -> g_partials[block]; the last block to finish
// folds the 256 partials into out[8] (single launch).
__global__ void __launch_bounds__(THREADS) masked_logp_kernel(
    const float* __restrict__ logits,   // [B,S,V] f32
    const int* __restrict__ a,          // [B,S]   i32
    const int* __restrict__ mask,       // [B,S,M] i32
    float* __restrict__ out)            // [B]     f32
{
    __shared__ float s_logp[ROWS_PER_BLOCK];
    __shared__ bool  s_last;

    const int warp = threadIdx.x >> 5;
    const int lane = threadIdx.x & 31;
    const int row  = blockIdx.x * ROWS_PER_BLOCK + warp;

    const float* __restrict__ lrow = logits + (size_t)row * VV;

    // Hoist the action-token chain so both DRAM rounds overlap.
    const int ai = (lane == 0) ? __ldg(a + row) : 0;
    float la = 0.0f;
    bool take = false;
    if (lane == 0 && ai != PAD_ID) {
        take = true;
        la = __ldcs(lrow + ai);            // single-use: streaming load
    }

    // Gather candidate logit for this lane's mask id (single-use -> evict-first).
    const int mid = __ldg(mask + (size_t)row * MM + lane);
    const bool valid = (mid > 0);
    float g = valid ? __ldcs(lrow + mid) : -__int_as_float(0x7f800000); // -inf

    // Warp max over gathered logits.
    float m = g;
    #pragma unroll
    for (int o = 16; o > 0; o >>= 1)
        m = fmaxf(m, __shfl_xor_sync(0xffffffffu, m, o));

    // Warp sum of exp(g - m) over valid lanes.
    float e = valid ? __expf(g - m) : 0.0f;
    #pragma unroll
    for (int o = 16; o > 0; o >>= 1)
        e += __shfl_xor_sync(0xffffffffu, e, o);

    if (lane == 0)
        s_logp[warp] = take ? (la - (m + __logf(e))) : 0.0f;

    __syncthreads();

    // Warp 0: reduce 16 per-row values -> this block's partial, publish it,
    // and check whether we are the last block to finish.
    if (warp == 0) {
        float v = (lane < ROWS_PER_BLOCK) ? s_logp[lane] : 0.0f;
        #pragma unroll
        for (int o = 8; o > 0; o >>= 1)
            v += __shfl_xor_sync(0xffffffffu, v, o);
        if (lane == 0) {
            g_partials[blockIdx.x] = v;
            __threadfence();
            const unsigned int prev = atomicAdd(&g_done, 1u);
            s_last = (prev == NBLOCKS - 1);
        }
    }
    __syncthreads();

    // Last block folds all 256 partials into out[8] and resets the counter.
    if (s_last) {
        __threadfence();  // acquire: make all g_partials writes visible
        const int tid = threadIdx.x;
        if (tid < NBLOCKS) {
            float v = g_partials[tid];
            // 32 consecutive partials per batch element == one full warp.
            #pragma unroll
            for (int o = 16; o > 0; o >>= 1)
                v += __shfl_xor_sync(0xffffffffu, v, o);
            if (lane == 0)
                out[tid >> 5] = v;
        }
        if (tid == 0)
            g_done = 0;   // deterministic across graph replays
    }
}

extern "C" void kernel_launch(void* const* d_in, const int* in_sizes, int n_in,
                              void* d_out, int out_size) {
    const float* logits = (const float*)d_in[0];  // [8,512,32000] f32
    const int* a        = (const int*)d_in[1];    // [8,512]       i32
    const int* mask     = (const int*)d_in[2];    // [8,512,32]    i32
    float* out = (float*)d_out;                   // [8]           f32

    masked_logp_kernel<<<NBLOCKS, THREADS>>>(logits, a, mask, out);
}